// round 3
// baseline (speedup 1.0000x reference)
#include <cuda_runtime.h>
#include <math.h>

#define N_NODES 100000
#define N_EDGES 800000
#define E_TOT   900000   // edges + self loops
#define NH 128
#define NC 2
#define NG 16

// ---------------- scratch (device globals; no allocation) ----------------
__device__ int   g_is64;
__device__ int   g_row[E_TOT];
__device__ int   g_col[E_TOT];
__device__ float g_norm[E_TOT];
__device__ float g_deg[N_NODES];           // becomes dinv in-place
__device__ int   g_batch[N_NODES];
__device__ float g_hlin[(size_t)N_NODES * NH];  // x@W1
__device__ float g_acc [(size_t)N_NODES * NH];  // scatter target / layer1 out
__device__ float g_t   [N_NODES * NC];          // h@W2
__device__ float g_acc2[N_NODES * NC];          // layer2 scatter target
__device__ float g_pool[NG * NC];
__device__ float g_cnt [NG];

// ---------------- kernels ----------------

// Detect int64 vs int32 index dtype: for int64 (values < 2^31, nonneg) every
// odd 32-bit word is 0; for random int32 indices in [0,1e5) that's impossible
// over 256 samples.
__global__ void k_detect(const unsigned int* __restrict__ e) {
    int is64 = 1;
    for (int i = 0; i < 256; i++) if (e[2 * i + 1] != 0u) { is64 = 0; break; }
    g_is64 = is64;
}

__global__ void k_zero() {
    size_t i = (size_t)blockIdx.x * blockDim.x + threadIdx.x;
    size_t stride = (size_t)gridDim.x * blockDim.x;
    for (size_t j = i; j < (size_t)N_NODES * NH; j += stride) g_acc[j] = 0.f;
    if (i < N_NODES * NC) g_acc2[i] = 0.f;
    if (i < N_NODES)      g_deg[i] = 0.f;
    if (i < NG * NC)      g_pool[i] = 0.f;
    if (i < NG)           g_cnt[i] = 0.f;
}

__global__ void k_cvt_batch(const void* __restrict__ bp) {
    int i = blockIdx.x * blockDim.x + threadIdx.x;
    if (i >= N_NODES) return;
    g_batch[i] = g_is64 ? (int)((const long long*)bp)[i] : ((const int*)bp)[i];
}

__global__ void k_build(const void* __restrict__ ep) {
    int e = blockIdx.x * blockDim.x + threadIdx.x;
    if (e >= E_TOT) return;
    int r, c;
    if (e < N_EDGES) {
        if (g_is64) { const long long* p = (const long long*)ep; r = (int)p[e]; c = (int)p[N_EDGES + e]; }
        else        { const int*       p = (const int*)ep;       r = p[e];      c = p[N_EDGES + e]; }
    } else {
        r = c = e - N_EDGES;  // self loop
    }
    g_row[e] = r; g_col[e] = c;
    atomicAdd(&g_deg[c], 1.0f);
}

__global__ void k_rsqrt() {
    int i = blockIdx.x * blockDim.x + threadIdx.x;
    if (i < N_NODES) {
        float d = g_deg[i];
        g_deg[i] = (d > 0.f) ? rsqrtf(d) : 0.f;
    }
}

__global__ void k_norm() {
    int e = blockIdx.x * blockDim.x + threadIdx.x;
    if (e < E_TOT) g_norm[e] = g_deg[g_row[e]] * g_deg[g_col[e]];
}

// h = x @ W1  (100000x128 @ 128x128), 64-row x 128-col tile per block
__global__ __launch_bounds__(256) void k_gemm1(const float* __restrict__ x,
                                               const float* __restrict__ W) {
    __shared__ float As[64][33];
    __shared__ float Bs[32][128];
    int tid = threadIdx.x;
    int tx = tid & 31, ty = tid >> 5;
    int row0 = blockIdx.x * 64;
    float acc[8][4];
#pragma unroll
    for (int i = 0; i < 8; i++)
#pragma unroll
        for (int j = 0; j < 4; j++) acc[i][j] = 0.f;

    for (int k0 = 0; k0 < 128; k0 += 32) {
#pragma unroll
        for (int t = 0; t < 8; t++) {
            int li = tid + t * 256;
            int r = li >> 5, k = li & 31;
            int gr = row0 + r;
            As[r][k] = (gr < N_NODES) ? x[(size_t)gr * 128 + k0 + k] : 0.f;
        }
#pragma unroll
        for (int t = 0; t < 16; t++) {
            int li = tid + t * 256;
            int k = li >> 7, n = li & 127;
            Bs[k][n] = W[(k0 + k) * 128 + n];
        }
        __syncthreads();
#pragma unroll
        for (int kk = 0; kk < 32; kk++) {
            float4 b = *(const float4*)&Bs[kk][tx * 4];
#pragma unroll
            for (int i = 0; i < 8; i++) {
                float a = As[ty * 8 + i][kk];
                acc[i][0] += a * b.x; acc[i][1] += a * b.y;
                acc[i][2] += a * b.z; acc[i][3] += a * b.w;
            }
        }
        __syncthreads();
    }
#pragma unroll
    for (int i = 0; i < 8; i++) {
        int gr = row0 + ty * 8 + i;
        if (gr < N_NODES) {
            float4 v = make_float4(acc[i][0], acc[i][1], acc[i][2], acc[i][3]);
            *(float4*)&g_hlin[(size_t)gr * 128 + tx * 4] = v;
        }
    }
}

// warp-per-edge gather/scale/scatter of 128 floats
__global__ void k_scatter1() {
    long long idx = (long long)blockIdx.x * blockDim.x + threadIdx.x;
    if (idx >= (long long)E_TOT * 32) return;
    int e = (int)(idx >> 5), g = (int)(idx & 31);
    int r = g_row[e], c = g_col[e];
    float nr = g_norm[e];
    float4 v = *(const float4*)&g_hlin[(size_t)r * 128 + g * 4];
    float* dst = &g_acc[(size_t)c * 128 + g * 4];
    atomicAdd(dst + 0, v.x * nr);
    atomicAdd(dst + 1, v.y * nr);
    atomicAdd(dst + 2, v.z * nr);
    atomicAdd(dst + 3, v.w * nr);
}

__global__ void k_bias_relu(const float* __restrict__ b1) {
    size_t i = (size_t)blockIdx.x * blockDim.x + threadIdx.x;
    if (i < (size_t)N_NODES * NH) {
        float v = g_acc[i] + b1[i & 127];
        g_acc[i] = v > 0.f ? v : 0.f;
    }
}

// t = h @ W2 (128 -> 2), warp per node
__global__ void k_gemm2(const float* __restrict__ W2) {
    int gt = blockIdx.x * blockDim.x + threadIdx.x;
    int w = gt >> 5, lane = gt & 31;
    if (w >= N_NODES) return;
    float4 h = *(const float4*)&g_acc[(size_t)w * 128 + lane * 4];
    const float* hp = (const float*)&h;
    float a0 = 0.f, a1 = 0.f;
#pragma unroll
    for (int j = 0; j < 4; j++) {
        int k = lane * 4 + j;
        a0 += hp[j] * W2[k * 2 + 0];
        a1 += hp[j] * W2[k * 2 + 1];
    }
#pragma unroll
    for (int s = 16; s > 0; s >>= 1) {
        a0 += __shfl_xor_sync(0xffffffffu, a0, s);
        a1 += __shfl_xor_sync(0xffffffffu, a1, s);
    }
    if (lane == 0) { g_t[w * 2] = a0; g_t[w * 2 + 1] = a1; }
}

__global__ void k_scatter2() {
    int e = blockIdx.x * blockDim.x + threadIdx.x;
    if (e >= E_TOT) return;
    float nr = g_norm[e];
    int r = g_row[e], c = g_col[e];
    float2 v = *(const float2*)&g_t[r * 2];
    atomicAdd(&g_acc2[c * 2 + 0], v.x * nr);
    atomicAdd(&g_acc2[c * 2 + 1], v.y * nr);
}

__global__ void k_pool() {
    __shared__ float sp[NG * NC];
    __shared__ float sc[NG];
    int tid = threadIdx.x;
    if (tid < NG * NC) sp[tid] = 0.f;
    if (tid < NG)      sc[tid] = 0.f;
    __syncthreads();
    int i = blockIdx.x * blockDim.x + tid;
    if (i < N_NODES) {
        int b = g_batch[i];
        float2 v = *(const float2*)&g_acc2[i * 2];
        atomicAdd(&sp[b * 2 + 0], v.x);
        atomicAdd(&sp[b * 2 + 1], v.y);
        atomicAdd(&sc[b], 1.f);
    }
    __syncthreads();
    if (tid < NG * NC) atomicAdd(&g_pool[tid], sp[tid]);
    if (tid < NG)      atomicAdd(&g_cnt[tid], sc[tid]);
}

__global__ void k_final(const float* __restrict__ b2, float* __restrict__ out) {
    int g = threadIdx.x;
    if (g >= NG) return;
    float cnt = g_cnt[g];
    float m = fmaxf(cnt, 1.0f);
    float p0 = (g_pool[g * 2 + 0] + cnt * b2[0]) / m;
    float p1 = (g_pool[g * 2 + 1] + cnt * b2[1]) / m;
    float mx = fmaxf(p0, p1);
    float lse = mx + logf(expf(p0 - mx) + expf(p1 - mx));
    out[g * 2 + 0] = p0 - lse;
    out[g * 2 + 1] = p1 - lse;
}

// ---------------- launch ----------------
extern "C" void kernel_launch(void* const* d_in, const int* in_sizes, int n_in,
                              void* d_out, int out_size) {
    const float* x     = (const float*)d_in[0];
    const void*  ei    = d_in[1];
    const void*  batch = d_in[2];
    const float* W1    = (const float*)d_in[3];
    const float* b1    = (const float*)d_in[4];
    const float* W2    = (const float*)d_in[5];
    const float* b2    = (const float*)d_in[6];
    float* out = (float*)d_out;

    k_detect<<<1, 1>>>((const unsigned int*)ei);
    k_zero<<<50000, 256>>>();
    k_cvt_batch<<<(N_NODES + 255) / 256, 256>>>(batch);
    k_build<<<(E_TOT + 255) / 256, 256>>>(ei);
    k_rsqrt<<<(N_NODES + 255) / 256, 256>>>();
    k_norm<<<(E_TOT + 255) / 256, 256>>>();
    k_gemm1<<<(N_NODES + 63) / 64, 256>>>(x, W1);
    k_scatter1<<<(int)(((long long)E_TOT * 32 + 255) / 256), 256>>>();
    k_bias_relu<<<(int)(((size_t)N_NODES * NH + 255) / 256), 256>>>(b1);
    k_gemm2<<<(N_NODES * 32 + 255) / 256, 256>>>(W2);
    k_scatter2<<<(E_TOT + 255) / 256, 256>>>();
    k_pool<<<(N_NODES + 255) / 256, 256>>>();
    k_final<<<1, 32>>>(b2, out);
}

// round 4
// speedup vs baseline: 2.1238x; 2.1238x over previous
#include <cuda_runtime.h>
#include <math.h>

#define N_NODES 100000
#define N_EDGES 800000
#define E_TOT   900000   // edges + self loops
#define NH 128
#define NC 2
#define NG 16
#define SCAN_BS 256
#define N_SCAN_BLK ((N_NODES + SCAN_BS - 1) / SCAN_BS)   // 391

// ---------------- scratch (device globals; no allocation) ----------------
__device__ int   g_is64;
__device__ int   g_row[E_TOT];
__device__ int   g_col[E_TOT];
__device__ int   g_cnt_hist[N_NODES];   // degree (incl. self loop)
__device__ int   g_ptr[N_NODES];        // CSR start
__device__ int   g_cursor[N_NODES];
__device__ int   g_blksum[512];
__device__ int   g_blkoff[512];
__device__ float g_dinv[N_NODES];
__device__ int   g_erow[E_TOT];         // source row per CSR slot
__device__ int   g_batch[N_NODES];
__device__ float g_aggx[(size_t)N_NODES * NH];  // Â x
__device__ float g_h   [(size_t)N_NODES * NH];  // relu((Âx)W1 + b1)
__device__ float g_t   [N_NODES * NC];          // h@W2
__device__ float g_pool[NG * NC];
__device__ float g_gcnt[NG];

// ---------------- kernels ----------------

// Detect int64 vs int32 index dtype.
__global__ void k_detect(const unsigned int* __restrict__ e) {
    int is64 = 1;
    for (int i = 0; i < 256; i++) if (e[2 * i + 1] != 0u) { is64 = 0; break; }
    g_is64 = is64;
}

__global__ void k_zero() {
    int i = blockIdx.x * blockDim.x + threadIdx.x;
    if (i < N_NODES) g_cnt_hist[i] = 0;
    if (i < NG * NC) g_pool[i] = 0.f;
    if (i < NG)      g_gcnt[i] = 0.f;
}

__global__ void k_cvt_batch(const void* __restrict__ bp) {
    int i = blockIdx.x * blockDim.x + threadIdx.x;
    if (i >= N_NODES) return;
    g_batch[i] = g_is64 ? (int)((const long long*)bp)[i] : ((const int*)bp)[i];
}

__global__ void k_build(const void* __restrict__ ep) {
    int e = blockIdx.x * blockDim.x + threadIdx.x;
    if (e >= E_TOT) return;
    int r, c;
    if (e < N_EDGES) {
        if (g_is64) { const long long* p = (const long long*)ep; r = (int)p[e]; c = (int)p[N_EDGES + e]; }
        else        { const int*       p = (const int*)ep;       r = p[e];      c = p[N_EDGES + e]; }
    } else {
        r = c = e - N_EDGES;  // self loop
    }
    g_row[e] = r; g_col[e] = c;
    atomicAdd(&g_cnt_hist[c], 1);
}

// two-level exclusive scan of g_cnt_hist -> g_ptr
__global__ void k_scan1() {
    __shared__ int s[SCAN_BS];
    int i = blockIdx.x * SCAN_BS + threadIdx.x;
    int v = (i < N_NODES) ? g_cnt_hist[i] : 0;
    s[threadIdx.x] = v;
    __syncthreads();
#pragma unroll
    for (int off = 1; off < SCAN_BS; off <<= 1) {
        int t = (threadIdx.x >= off) ? s[threadIdx.x - off] : 0;
        __syncthreads();
        s[threadIdx.x] += t;
        __syncthreads();
    }
    if (i < N_NODES) g_ptr[i] = s[threadIdx.x] - v;   // exclusive within block
    if (threadIdx.x == SCAN_BS - 1) g_blksum[blockIdx.x] = s[SCAN_BS - 1];
}

__global__ void k_scan2() {
    __shared__ int s[512];
    int v = (threadIdx.x < N_SCAN_BLK) ? g_blksum[threadIdx.x] : 0;
    s[threadIdx.x] = v;
    __syncthreads();
#pragma unroll
    for (int off = 1; off < 512; off <<= 1) {
        int t = (threadIdx.x >= off) ? s[threadIdx.x - off] : 0;
        __syncthreads();
        s[threadIdx.x] += t;
        __syncthreads();
    }
    g_blkoff[threadIdx.x] = s[threadIdx.x] - v;       // exclusive
}

__global__ void k_scan3() {
    int i = blockIdx.x * blockDim.x + threadIdx.x;
    if (i >= N_NODES) return;
    int p = g_ptr[i] + g_blkoff[i >> 8];
    g_ptr[i] = p;
    g_cursor[i] = p;
    float d = (float)g_cnt_hist[i];
    g_dinv[i] = (d > 0.f) ? rsqrtf(d) : 0.f;
}

__global__ void k_fill() {
    int e = blockIdx.x * blockDim.x + threadIdx.x;
    if (e >= E_TOT) return;
    int c = g_col[e];
    int slot = atomicAdd(&g_cursor[c], 1);
    g_erow[slot] = g_row[e];
}

// agg = Â x : warp per node, registers as accumulator, no atomics
__global__ __launch_bounds__(256) void k_agg1(const float* __restrict__ x) {
    int gt = blockIdx.x * blockDim.x + threadIdx.x;
    int w = gt >> 5, lane = gt & 31;
    if (w >= N_NODES) return;
    int start = g_ptr[w];
    int deg = g_cnt_hist[w];
    float4 acc = make_float4(0.f, 0.f, 0.f, 0.f);
    for (int j = 0; j < deg; j++) {
        int r = g_erow[start + j];
        float wt = g_dinv[r];
        float4 v = *(const float4*)&x[(size_t)r * 128 + lane * 4];
        acc.x += wt * v.x; acc.y += wt * v.y;
        acc.z += wt * v.z; acc.w += wt * v.w;
    }
    float dc = g_dinv[w];
    acc.x *= dc; acc.y *= dc; acc.z *= dc; acc.w *= dc;
    *(float4*)&g_aggx[(size_t)w * 128 + lane * 4] = acc;
}

// h = relu(agg @ W1 + b1)  (100000x128 @ 128x128), fused epilogue
__global__ __launch_bounds__(256) void k_gemm1(const float* __restrict__ b1,
                                               const float* __restrict__ W) {
    __shared__ float As[64][33];
    __shared__ float Bs[32][128];
    int tid = threadIdx.x;
    int tx = tid & 31, ty = tid >> 5;
    int row0 = blockIdx.x * 64;
    float acc[8][4];
#pragma unroll
    for (int i = 0; i < 8; i++)
#pragma unroll
        for (int j = 0; j < 4; j++) acc[i][j] = 0.f;

    for (int k0 = 0; k0 < 128; k0 += 32) {
#pragma unroll
        for (int t = 0; t < 8; t++) {
            int li = tid + t * 256;
            int r = li >> 5, k = li & 31;
            int gr = row0 + r;
            As[r][k] = (gr < N_NODES) ? g_aggx[(size_t)gr * 128 + k0 + k] : 0.f;
        }
#pragma unroll
        for (int t = 0; t < 16; t++) {
            int li = tid + t * 256;
            int k = li >> 7, n = li & 127;
            Bs[k][n] = W[(k0 + k) * 128 + n];
        }
        __syncthreads();
#pragma unroll
        for (int kk = 0; kk < 32; kk++) {
            float4 b = *(const float4*)&Bs[kk][tx * 4];
#pragma unroll
            for (int i = 0; i < 8; i++) {
                float a = As[ty * 8 + i][kk];
                acc[i][0] += a * b.x; acc[i][1] += a * b.y;
                acc[i][2] += a * b.z; acc[i][3] += a * b.w;
            }
        }
        __syncthreads();
    }
    float4 bias = *(const float4*)&b1[tx * 4];
#pragma unroll
    for (int i = 0; i < 8; i++) {
        int gr = row0 + ty * 8 + i;
        if (gr < N_NODES) {
            float4 v;
            v.x = fmaxf(acc[i][0] + bias.x, 0.f);
            v.y = fmaxf(acc[i][1] + bias.y, 0.f);
            v.z = fmaxf(acc[i][2] + bias.z, 0.f);
            v.w = fmaxf(acc[i][3] + bias.w, 0.f);
            *(float4*)&g_h[(size_t)gr * 128 + tx * 4] = v;
        }
    }
}

// t = h @ W2 (128 -> 2), warp per node
__global__ void k_gemm2(const float* __restrict__ W2) {
    int gt = blockIdx.x * blockDim.x + threadIdx.x;
    int w = gt >> 5, lane = gt & 31;
    if (w >= N_NODES) return;
    float4 h = *(const float4*)&g_h[(size_t)w * 128 + lane * 4];
    const float* hp = (const float*)&h;
    float a0 = 0.f, a1 = 0.f;
#pragma unroll
    for (int j = 0; j < 4; j++) {
        int k = lane * 4 + j;
        a0 += hp[j] * W2[k * 2 + 0];
        a1 += hp[j] * W2[k * 2 + 1];
    }
#pragma unroll
    for (int s = 16; s > 0; s >>= 1) {
        a0 += __shfl_xor_sync(0xffffffffu, a0, s);
        a1 += __shfl_xor_sync(0xffffffffu, a1, s);
    }
    if (lane == 0) { g_t[w * 2] = a0; g_t[w * 2 + 1] = a1; }
}

// layer-2 aggregation (CSR, no atomics) fused with mean-pool accumulation
__global__ void k_agg2_pool(const float* __restrict__ b2) {
    __shared__ float sp[NG * NC];
    __shared__ float sc[NG];
    int tid = threadIdx.x;
    if (tid < NG * NC) sp[tid] = 0.f;
    if (tid < NG)      sc[tid] = 0.f;
    __syncthreads();
    int i = blockIdx.x * blockDim.x + tid;
    if (i < N_NODES) {
        int start = g_ptr[i];
        int deg = g_cnt_hist[i];
        float a0 = 0.f, a1 = 0.f;
        for (int j = 0; j < deg; j++) {
            int r = g_erow[start + j];
            float wt = g_dinv[r];
            float2 v = *(const float2*)&g_t[r * 2];
            a0 += wt * v.x; a1 += wt * v.y;
        }
        float dc = g_dinv[i];
        a0 = a0 * dc + b2[0];
        a1 = a1 * dc + b2[1];
        int b = g_batch[i];
        atomicAdd(&sp[b * 2 + 0], a0);
        atomicAdd(&sp[b * 2 + 1], a1);
        atomicAdd(&sc[b], 1.f);
    }
    __syncthreads();
    if (tid < NG * NC && sp[tid] != 0.f) atomicAdd(&g_pool[tid], sp[tid]);
    if (tid < NG && sc[tid] != 0.f)      atomicAdd(&g_gcnt[tid], sc[tid]);
}

__global__ void k_final(float* __restrict__ out) {
    int g = threadIdx.x;
    if (g >= NG) return;
    float cnt = g_gcnt[g];
    float m = fmaxf(cnt, 1.0f);
    float p0 = g_pool[g * 2 + 0] / m;
    float p1 = g_pool[g * 2 + 1] / m;
    float mx = fmaxf(p0, p1);
    float lse = mx + logf(expf(p0 - mx) + expf(p1 - mx));
    out[g * 2 + 0] = p0 - lse;
    out[g * 2 + 1] = p1 - lse;
}

// ---------------- launch ----------------
extern "C" void kernel_launch(void* const* d_in, const int* in_sizes, int n_in,
                              void* d_out, int out_size) {
    const float* x     = (const float*)d_in[0];
    const void*  ei    = d_in[1];
    const void*  batch = d_in[2];
    const float* W1    = (const float*)d_in[3];
    const float* b1    = (const float*)d_in[4];
    const float* W2    = (const float*)d_in[5];
    const float* b2    = (const float*)d_in[6];
    float* out = (float*)d_out;

    k_detect<<<1, 1>>>((const unsigned int*)ei);
    k_zero<<<(N_NODES + 255) / 256, 256>>>();
    k_cvt_batch<<<(N_NODES + 255) / 256, 256>>>(batch);
    k_build<<<(E_TOT + 255) / 256, 256>>>(ei);
    k_scan1<<<N_SCAN_BLK, SCAN_BS>>>();
    k_scan2<<<1, 512>>>();
    k_scan3<<<(N_NODES + 255) / 256, 256>>>();
    k_fill<<<(E_TOT + 255) / 256, 256>>>();
    k_agg1<<<(N_NODES * 32 + 255) / 256, 256>>>(x);
    k_gemm1<<<(N_NODES + 63) / 64, 256>>>(b1, W1);
    k_gemm2<<<(N_NODES * 32 + 255) / 256, 256>>>(W2);
    k_agg2_pool<<<(N_NODES + 255) / 256, 256>>>(b2);
    k_final<<<1, 32>>>(out);
}

// round 5
// speedup vs baseline: 2.8691x; 1.3509x over previous
#include <cuda_runtime.h>
#include <math.h>

#define N_NODES 100000
#define N_EDGES 800000
#define E_TOT   900000   // edges + self loops
#define NH 128
#define NC 2
#define NG 16
#define SCAN_BS 256
#define N_SCAN_BLK ((N_NODES + SCAN_BS - 1) / SCAN_BS)   // 391

// ---------------- scratch (device globals; no allocation) ----------------
__device__ int   g_is64;
__device__ int   g_row[E_TOT];
__device__ int   g_col[E_TOT];
__device__ int   g_cnt_hist[N_NODES];   // degree (incl. self loop)
__device__ int   g_ptr[N_NODES];        // CSR start
__device__ int   g_cursor[N_NODES];
__device__ int   g_blksum[512];
__device__ int   g_blkoff[512];
__device__ float g_dinv[N_NODES];
__device__ int   g_erow[E_TOT];         // source row per CSR slot
__device__ int   g_batch[N_NODES];
__device__ float g_t[N_NODES * NC];     // h@W2 (atomic partial sums)
__device__ float g_pool[NG * NC];
__device__ float g_gcnt[NG];

// ---------------- helpers ----------------
__device__ __forceinline__ unsigned tf32cvt(float f) {
    unsigned u;
    asm("cvt.rna.tf32.f32 %0, %1;" : "=r"(u) : "f"(f));
    return u;
}

__device__ __forceinline__ void mma_tf32(float* d, unsigned a0, unsigned a1,
                                         unsigned a2, unsigned a3,
                                         unsigned b0, unsigned b1) {
    asm volatile(
        "mma.sync.aligned.m16n8k8.row.col.f32.tf32.tf32.f32 "
        "{%0,%1,%2,%3}, {%4,%5,%6,%7}, {%8,%9}, {%0,%1,%2,%3};"
        : "+f"(d[0]), "+f"(d[1]), "+f"(d[2]), "+f"(d[3])
        : "r"(a0), "r"(a1), "r"(a2), "r"(a3), "r"(b0), "r"(b1));
}

// ---------------- kernels ----------------

// Detect int64 vs int32 index dtype.
__global__ void k_detect(const unsigned int* __restrict__ e) {
    int is64 = 1;
    for (int i = 0; i < 256; i++) if (e[2 * i + 1] != 0u) { is64 = 0; break; }
    g_is64 = is64;
}

// zero scratch + convert batch ids
__global__ void k_zero_cvt(const void* __restrict__ bp) {
    int i = blockIdx.x * blockDim.x + threadIdx.x;
    if (i < N_NODES) {
        g_cnt_hist[i] = 0;
        g_t[2 * i + 0] = 0.f;
        g_t[2 * i + 1] = 0.f;
        g_batch[i] = g_is64 ? (int)((const long long*)bp)[i] : ((const int*)bp)[i];
    }
    if (i < NG * NC) g_pool[i] = 0.f;
    if (i < NG)      g_gcnt[i] = 0.f;
}

__global__ void k_build(const void* __restrict__ ep) {
    int e = blockIdx.x * blockDim.x + threadIdx.x;
    if (e >= E_TOT) return;
    int r, c;
    if (e < N_EDGES) {
        if (g_is64) { const long long* p = (const long long*)ep; r = (int)p[e]; c = (int)p[N_EDGES + e]; }
        else        { const int*       p = (const int*)ep;       r = p[e];      c = p[N_EDGES + e]; }
    } else {
        r = c = e - N_EDGES;  // self loop
    }
    g_row[e] = r; g_col[e] = c;
    atomicAdd(&g_cnt_hist[c], 1);
}

// two-level exclusive scan of g_cnt_hist -> g_ptr
__global__ void k_scan1() {
    __shared__ int s[SCAN_BS];
    int i = blockIdx.x * SCAN_BS + threadIdx.x;
    int v = (i < N_NODES) ? g_cnt_hist[i] : 0;
    s[threadIdx.x] = v;
    __syncthreads();
#pragma unroll
    for (int off = 1; off < SCAN_BS; off <<= 1) {
        int t = (threadIdx.x >= off) ? s[threadIdx.x - off] : 0;
        __syncthreads();
        s[threadIdx.x] += t;
        __syncthreads();
    }
    if (i < N_NODES) g_ptr[i] = s[threadIdx.x] - v;
    if (threadIdx.x == SCAN_BS - 1) g_blksum[blockIdx.x] = s[SCAN_BS - 1];
}

__global__ void k_scan2() {
    __shared__ int s[512];
    int v = (threadIdx.x < N_SCAN_BLK) ? g_blksum[threadIdx.x] : 0;
    s[threadIdx.x] = v;
    __syncthreads();
#pragma unroll
    for (int off = 1; off < 512; off <<= 1) {
        int t = (threadIdx.x >= off) ? s[threadIdx.x - off] : 0;
        __syncthreads();
        s[threadIdx.x] += t;
        __syncthreads();
    }
    g_blkoff[threadIdx.x] = s[threadIdx.x] - v;
}

__global__ void k_scan3() {
    int i = blockIdx.x * blockDim.x + threadIdx.x;
    if (i >= N_NODES) return;
    int p = g_ptr[i] + g_blkoff[i >> 8];
    g_ptr[i] = p;
    g_cursor[i] = p;
    float d = (float)g_cnt_hist[i];
    g_dinv[i] = (d > 0.f) ? rsqrtf(d) : 0.f;
}

__global__ void k_fill() {
    int e = blockIdx.x * blockDim.x + threadIdx.x;
    if (e >= E_TOT) return;
    int c = g_col[e];
    int slot = atomicAdd(&g_cursor[c], 1);
    g_erow[slot] = g_row[e];
}

// ---------------------------------------------------------------------------
// Fused: aggregate (Â x) into smem (tf32), TF32 tensor-core GEMM with W1,
// epilogue bias+ReLU, then project by W2 in-register and atomically
// accumulate t = h @ W2 into g_t. Neither Âx nor h ever touch global memory.
// Block: 256 thr (8 warps), tile 64 rows x 128 cols.
// ---------------------------------------------------------------------------
__global__ __launch_bounds__(256, 2) void k_fused(const float* __restrict__ x,
                                                  const float* __restrict__ W1,
                                                  const float* __restrict__ b1,
                                                  const float* __restrict__ W2) {
    __shared__ unsigned As[64][132];   // tf32 aggregated features (528B row stride, 16B aligned)
    __shared__ unsigned Ws[16][132];   // tf32 W1 k-chunk
    __shared__ float W2s[NH * NC];
    __shared__ float b1s[NH];

    int tid = threadIdx.x, wid = tid >> 5, lane = tid & 31;
    int row0 = blockIdx.x * 64;

    if (tid < NH) b1s[tid] = b1[tid];
    W2s[tid] = W2[tid];   // 256 threads, 256 elements

    // ---- stage A: aggregation, warp per node (8 nodes per warp) ----
    for (int i = 0; i < 8; i++) {
        int rl = wid * 8 + i;
        int node = row0 + rl;
        float4 acc = make_float4(0.f, 0.f, 0.f, 0.f);
        if (node < N_NODES) {
            int start = g_ptr[node];
            int deg = g_cnt_hist[node];
            float dc = g_dinv[node];
            int j = 0;
            for (; j + 2 <= deg; j += 2) {            // 2-deep MLP
                int r0 = g_erow[start + j];
                int r1 = g_erow[start + j + 1];
                float w0 = g_dinv[r0], w1 = g_dinv[r1];
                float4 v0 = *(const float4*)&x[(size_t)r0 * NH + lane * 4];
                float4 v1 = *(const float4*)&x[(size_t)r1 * NH + lane * 4];
                acc.x += w0 * v0.x + w1 * v1.x;
                acc.y += w0 * v0.y + w1 * v1.y;
                acc.z += w0 * v0.z + w1 * v1.z;
                acc.w += w0 * v0.w + w1 * v1.w;
            }
            if (j < deg) {
                int r0 = g_erow[start + j];
                float w0 = g_dinv[r0];
                float4 v0 = *(const float4*)&x[(size_t)r0 * NH + lane * 4];
                acc.x += w0 * v0.x; acc.y += w0 * v0.y;
                acc.z += w0 * v0.z; acc.w += w0 * v0.w;
            }
            acc.x *= dc; acc.y *= dc; acc.z *= dc; acc.w *= dc;
        }
        uint4 u;
        u.x = tf32cvt(acc.x); u.y = tf32cvt(acc.y);
        u.z = tf32cvt(acc.z); u.w = tf32cvt(acc.w);
        *(uint4*)&As[rl][lane * 4] = u;
    }
    __syncthreads();

    // ---- stage B: TF32 MMA. warp grid 4(m) x 2(n); warp tile 16 x 64 ----
    int wm = wid >> 1, wn = wid & 1;
    int g = lane >> 2, t4 = lane & 3;
    float acc[8][4];
#pragma unroll
    for (int t = 0; t < 8; t++)
#pragma unroll
        for (int j = 0; j < 4; j++) acc[t][j] = 0.f;

    for (int chunk = 0; chunk < 8; chunk++) {   // K in chunks of 16
#pragma unroll
        for (int t = 0; t < 8; t++) {
            int li = tid + t * 256;
            int k = li >> 7, n = li & 127;
            Ws[k][n] = tf32cvt(W1[(chunk * 16 + k) * 128 + n]);
        }
        __syncthreads();
#pragma unroll
        for (int ks = 0; ks < 2; ks++) {
            int kb = chunk * 16 + ks * 8;
            unsigned a0 = As[wm * 16 + g][kb + t4];
            unsigned a1 = As[wm * 16 + g + 8][kb + t4];
            unsigned a2 = As[wm * 16 + g][kb + t4 + 4];
            unsigned a3 = As[wm * 16 + g + 8][kb + t4 + 4];
#pragma unroll
            for (int tile = 0; tile < 8; tile++) {
                int n0 = wn * 64 + tile * 8;
                unsigned b0 = Ws[ks * 8 + t4][n0 + g];
                unsigned bb = Ws[ks * 8 + t4 + 4][n0 + g];
                mma_tf32(acc[tile], a0, a1, a2, a3, b0, bb);
            }
        }
        __syncthreads();
    }

    // ---- epilogue: bias + ReLU + W2 projection, all in registers ----
    float tA0 = 0.f, tA1 = 0.f, tB0 = 0.f, tB1 = 0.f;
#pragma unroll
    for (int tile = 0; tile < 8; tile++) {
        int c0 = wn * 64 + tile * 8 + t4 * 2;
        float bias0 = b1s[c0], bias1 = b1s[c0 + 1];
        float h00 = fmaxf(acc[tile][0] + bias0, 0.f);   // row g,   col c0
        float h01 = fmaxf(acc[tile][1] + bias1, 0.f);   // row g,   col c0+1
        float h10 = fmaxf(acc[tile][2] + bias0, 0.f);   // row g+8, col c0
        float h11 = fmaxf(acc[tile][3] + bias1, 0.f);   // row g+8, col c0+1
        float w00 = W2s[c0 * 2 + 0], w01 = W2s[c0 * 2 + 1];
        float w10 = W2s[(c0 + 1) * 2 + 0], w11 = W2s[(c0 + 1) * 2 + 1];
        tA0 += h00 * w00 + h01 * w10;
        tA1 += h00 * w01 + h01 * w11;
        tB0 += h10 * w00 + h11 * w10;
        tB1 += h10 * w01 + h11 * w11;
    }
    // reduce over the 4 lanes sharing a row (t4 = 0..3)
    tA0 += __shfl_xor_sync(0xffffffffu, tA0, 1); tA0 += __shfl_xor_sync(0xffffffffu, tA0, 2);
    tA1 += __shfl_xor_sync(0xffffffffu, tA1, 1); tA1 += __shfl_xor_sync(0xffffffffu, tA1, 2);
    tB0 += __shfl_xor_sync(0xffffffffu, tB0, 1); tB0 += __shfl_xor_sync(0xffffffffu, tB0, 2);
    tB1 += __shfl_xor_sync(0xffffffffu, tB1, 1); tB1 += __shfl_xor_sync(0xffffffffu, tB1, 2);
    if (t4 == 0) {
        int rA = row0 + wm * 16 + g;
        int rB = rA + 8;
        if (rA < N_NODES) {
            atomicAdd(&g_t[rA * 2 + 0], tA0);
            atomicAdd(&g_t[rA * 2 + 1], tA1);
        }
        if (rB < N_NODES) {
            atomicAdd(&g_t[rB * 2 + 0], tB0);
            atomicAdd(&g_t[rB * 2 + 1], tB1);
        }
    }
}

// layer-2 aggregation (CSR, no atomics) fused with mean-pool accumulation
__global__ void k_agg2_pool(const float* __restrict__ b2) {
    __shared__ float sp[NG * NC];
    __shared__ float sc[NG];
    int tid = threadIdx.x;
    if (tid < NG * NC) sp[tid] = 0.f;
    if (tid < NG)      sc[tid] = 0.f;
    __syncthreads();
    int i = blockIdx.x * blockDim.x + tid;
    if (i < N_NODES) {
        int start = g_ptr[i];
        int deg = g_cnt_hist[i];
        float a0 = 0.f, a1 = 0.f;
        for (int j = 0; j < deg; j++) {
            int r = g_erow[start + j];
            float wt = g_dinv[r];
            float2 v = *(const float2*)&g_t[r * 2];
            a0 += wt * v.x; a1 += wt * v.y;
        }
        float dc = g_dinv[i];
        a0 = a0 * dc + b2[0];
        a1 = a1 * dc + b2[1];
        int b = g_batch[i];
        atomicAdd(&sp[b * 2 + 0], a0);
        atomicAdd(&sp[b * 2 + 1], a1);
        atomicAdd(&sc[b], 1.f);
    }
    __syncthreads();
    if (tid < NG * NC && sp[tid] != 0.f) atomicAdd(&g_pool[tid], sp[tid]);
    if (tid < NG && sc[tid] != 0.f)      atomicAdd(&g_gcnt[tid], sc[tid]);
}

__global__ void k_final(float* __restrict__ out) {
    int g = threadIdx.x;
    if (g >= NG) return;
    float cnt = g_gcnt[g];
    float m = fmaxf(cnt, 1.0f);
    float p0 = g_pool[g * 2 + 0] / m;
    float p1 = g_pool[g * 2 + 1] / m;
    float mx = fmaxf(p0, p1);
    float lse = mx + logf(expf(p0 - mx) + expf(p1 - mx));
    out[g * 2 + 0] = p0 - lse;
    out[g * 2 + 1] = p1 - lse;
}

// ---------------- launch ----------------
extern "C" void kernel_launch(void* const* d_in, const int* in_sizes, int n_in,
                              void* d_out, int out_size) {
    const float* x     = (const float*)d_in[0];
    const void*  ei    = d_in[1];
    const void*  batch = d_in[2];
    const float* W1    = (const float*)d_in[3];
    const float* b1    = (const float*)d_in[4];
    const float* W2    = (const float*)d_in[5];
    const float* b2    = (const float*)d_in[6];
    float* out = (float*)d_out;

    k_detect<<<1, 1>>>((const unsigned int*)ei);
    k_zero_cvt<<<(N_NODES + 255) / 256, 256>>>(batch);
    k_build<<<(E_TOT + 255) / 256, 256>>>(ei);
    k_scan1<<<N_SCAN_BLK, SCAN_BS>>>();
    k_scan2<<<1, 512>>>();
    k_scan3<<<(N_NODES + 255) / 256, 256>>>();
    k_fill<<<(E_TOT + 255) / 256, 256>>>();
    k_fused<<<(N_NODES + 63) / 64, 256>>>(x, W1, b1, W2);
    k_agg2_pool<<<(N_NODES + 255) / 256, 256>>>(b2);
    k_final<<<1, 32>>>(out);
}

// round 6
// speedup vs baseline: 3.3098x; 1.1536x over previous
#include <cuda_runtime.h>
#include <math.h>

#define N_NODES 100000
#define N_EDGES 800000
#define E_TOT   900000   // edges + self loops
#define NH 128
#define NC 2
#define NG 16
#define SCAN_BS 256
#define N_SCAN_BLK ((N_NODES + SCAN_BS - 1) / SCAN_BS)   // 391

// ---------------- scratch (device globals; no allocation) ----------------
__device__ int   g_is64;
__device__ int   g_row[E_TOT];
__device__ int   g_col[E_TOT];
__device__ int   g_cnt_hist[N_NODES];   // degree (incl. self loop)
__device__ int   g_ptr[N_NODES];        // CSR start
__device__ int   g_cursor[N_NODES];
__device__ int   g_blksum[512];
__device__ int   g_blkoff[512];
__device__ float g_dinv[N_NODES];
__device__ int   g_erow[E_TOT];         // source row per CSR slot
__device__ int   g_batch[N_NODES];
__device__ float g_t[N_NODES * NC];     // h@W2 (atomic partial sums)
__device__ float g_pool[NG * NC];
__device__ float g_gcnt[NG];

// ---------------- helpers ----------------
__device__ __forceinline__ unsigned tf32cvt(float f) {
    unsigned u;
    asm("cvt.rna.tf32.f32 %0, %1;" : "=r"(u) : "f"(f));
    return u;
}

__device__ __forceinline__ void mma_tf32(float* d, unsigned a0, unsigned a1,
                                         unsigned a2, unsigned a3,
                                         unsigned b0, unsigned b1) {
    asm volatile(
        "mma.sync.aligned.m16n8k8.row.col.f32.tf32.tf32.f32 "
        "{%0,%1,%2,%3}, {%4,%5,%6,%7}, {%8,%9}, {%0,%1,%2,%3};"
        : "+f"(d[0]), "+f"(d[1]), "+f"(d[2]), "+f"(d[3])
        : "r"(a0), "r"(a1), "r"(a2), "r"(a3), "r"(b0), "r"(b1));
}

__device__ __forceinline__ int warp_incl_scan(int v, int lane) {
#pragma unroll
    for (int off = 1; off < 32; off <<= 1) {
        int t = __shfl_up_sync(0xffffffffu, v, off);
        if (lane >= off) v += t;
    }
    return v;
}

// ---------------- kernels ----------------

// Detect int64 vs int32 index dtype: warp-parallel (was a serial 1-thread loop).
__global__ void k_detect(const unsigned int* __restrict__ e) {
    int lane = threadIdx.x;
    unsigned v = 0;
#pragma unroll
    for (int i = 0; i < 8; i++) v |= e[2 * (lane + 32 * i) + 1];
    int any = __any_sync(0xffffffffu, v != 0u);
    if (lane == 0) g_is64 = !any;
}

// zero scratch + convert batch ids
__global__ void k_zero_cvt(const void* __restrict__ bp) {
    int i = blockIdx.x * blockDim.x + threadIdx.x;
    if (i < N_NODES) {
        g_cnt_hist[i] = 0;
        g_t[2 * i + 0] = 0.f;
        g_t[2 * i + 1] = 0.f;
        g_batch[i] = g_is64 ? (int)((const long long*)bp)[i] : ((const int*)bp)[i];
    }
    if (i < NG * NC) g_pool[i] = 0.f;
    if (i < NG)      g_gcnt[i] = 0.f;
}

__global__ void k_build(const void* __restrict__ ep) {
    int e = blockIdx.x * blockDim.x + threadIdx.x;
    if (e >= E_TOT) return;
    int r, c;
    if (e < N_EDGES) {
        if (g_is64) { const long long* p = (const long long*)ep; r = (int)p[e]; c = (int)p[N_EDGES + e]; }
        else        { const int*       p = (const int*)ep;       r = p[e];      c = p[N_EDGES + e]; }
    } else {
        r = c = e - N_EDGES;  // self loop
    }
    g_row[e] = r; g_col[e] = c;
    atomicAdd(&g_cnt_hist[c], 1);
}

// two-level exclusive scan of g_cnt_hist -> g_ptr (shuffle-based)
__global__ void k_scan1() {
    __shared__ int wsum[8];
    int tid = threadIdx.x, lane = tid & 31, wid = tid >> 5;
    int i = blockIdx.x * SCAN_BS + tid;
    int v = (i < N_NODES) ? g_cnt_hist[i] : 0;
    int s = warp_incl_scan(v, lane);
    if (lane == 31) wsum[wid] = s;
    __syncthreads();
    if (wid == 0) {
        int w = (lane < 8) ? wsum[lane] : 0;
        w = warp_incl_scan(w, lane);
        if (lane < 8) wsum[lane] = w;
    }
    __syncthreads();
    int base = (wid > 0) ? wsum[wid - 1] : 0;
    if (i < N_NODES) g_ptr[i] = base + s - v;   // exclusive within block
    if (tid == SCAN_BS - 1) g_blksum[blockIdx.x] = base + s;
}

__global__ void k_scan2() {
    __shared__ int wsum[16];
    int tid = threadIdx.x, lane = tid & 31, wid = tid >> 5;
    int v = (tid < N_SCAN_BLK) ? g_blksum[tid] : 0;
    int s = warp_incl_scan(v, lane);
    if (lane == 31) wsum[wid] = s;
    __syncthreads();
    if (wid == 0) {
        int w = (lane < 16) ? wsum[lane] : 0;
        w = warp_incl_scan(w, lane);
        if (lane < 16) wsum[lane] = w;
    }
    __syncthreads();
    int base = (wid > 0) ? wsum[wid - 1] : 0;
    g_blkoff[tid] = base + s - v;               // exclusive
}

__global__ void k_scan3() {
    int i = blockIdx.x * blockDim.x + threadIdx.x;
    if (i >= N_NODES) return;
    int p = g_ptr[i] + g_blkoff[i >> 8];
    g_ptr[i] = p;
    g_cursor[i] = p;
    float d = (float)g_cnt_hist[i];
    g_dinv[i] = (d > 0.f) ? rsqrtf(d) : 0.f;
}

__global__ void k_fill() {
    int e = blockIdx.x * blockDim.x + threadIdx.x;
    if (e >= E_TOT) return;
    int c = g_col[e];
    int slot = atomicAdd(&g_cursor[c], 1);
    g_erow[slot] = g_row[e];
}

// ---------------------------------------------------------------------------
// Fused: aggregate (Â x) into smem (tf32), TF32 tensor-core GEMM with W1,
// epilogue bias+ReLU, then project by W2 in-register and atomically
// accumulate t = h @ W2 into g_t.
// ---------------------------------------------------------------------------
__global__ __launch_bounds__(256, 3) void k_fused(const float* __restrict__ x,
                                                  const float* __restrict__ W1,
                                                  const float* __restrict__ b1,
                                                  const float* __restrict__ W2) {
    __shared__ unsigned As[64][132];   // tf32 aggregated features
    __shared__ unsigned Ws[16][132];   // tf32 W1 k-chunk
    __shared__ float W2s[NH * NC];
    __shared__ float b1s[NH];

    int tid = threadIdx.x, wid = tid >> 5, lane = tid & 31;
    int row0 = blockIdx.x * 64;

    if (tid < NH) b1s[tid] = b1[tid];
    W2s[tid] = W2[tid];

    // ---- stage A: aggregation, warp per node, 4-deep edge unroll ----
    for (int i = 0; i < 8; i++) {
        int rl = wid * 8 + i;
        int node = row0 + rl;
        float4 acc = make_float4(0.f, 0.f, 0.f, 0.f);
        if (node < N_NODES) {
            int start = g_ptr[node];
            int deg = g_cnt_hist[node];
            float dc = g_dinv[node];
            int j = 0;
            for (; j + 4 <= deg; j += 4) {
                int r0 = g_erow[start + j];
                int r1 = g_erow[start + j + 1];
                int r2 = g_erow[start + j + 2];
                int r3 = g_erow[start + j + 3];
                float w0 = g_dinv[r0], w1 = g_dinv[r1];
                float w2 = g_dinv[r2], w3 = g_dinv[r3];
                float4 v0 = *(const float4*)&x[(size_t)r0 * NH + lane * 4];
                float4 v1 = *(const float4*)&x[(size_t)r1 * NH + lane * 4];
                float4 v2 = *(const float4*)&x[(size_t)r2 * NH + lane * 4];
                float4 v3 = *(const float4*)&x[(size_t)r3 * NH + lane * 4];
                acc.x += w0 * v0.x + w1 * v1.x + w2 * v2.x + w3 * v3.x;
                acc.y += w0 * v0.y + w1 * v1.y + w2 * v2.y + w3 * v3.y;
                acc.z += w0 * v0.z + w1 * v1.z + w2 * v2.z + w3 * v3.z;
                acc.w += w0 * v0.w + w1 * v1.w + w2 * v2.w + w3 * v3.w;
            }
            for (; j < deg; j++) {
                int r0 = g_erow[start + j];
                float w0 = g_dinv[r0];
                float4 v0 = *(const float4*)&x[(size_t)r0 * NH + lane * 4];
                acc.x += w0 * v0.x; acc.y += w0 * v0.y;
                acc.z += w0 * v0.z; acc.w += w0 * v0.w;
            }
            acc.x *= dc; acc.y *= dc; acc.z *= dc; acc.w *= dc;
        }
        uint4 u;
        u.x = tf32cvt(acc.x); u.y = tf32cvt(acc.y);
        u.z = tf32cvt(acc.z); u.w = tf32cvt(acc.w);
        *(uint4*)&As[rl][lane * 4] = u;
    }
    __syncthreads();

    // ---- stage B: TF32 MMA. warp grid 4(m) x 2(n); warp tile 16 x 64 ----
    int wm = wid >> 1, wn = wid & 1;
    int g = lane >> 2, t4 = lane & 3;
    float acc[8][4];
#pragma unroll
    for (int t = 0; t < 8; t++)
#pragma unroll
        for (int j = 0; j < 4; j++) acc[t][j] = 0.f;

    for (int chunk = 0; chunk < 8; chunk++) {   // K in chunks of 16
#pragma unroll
        for (int t = 0; t < 8; t++) {
            int li = tid + t * 256;
            int k = li >> 7, n = li & 127;
            Ws[k][n] = tf32cvt(W1[(chunk * 16 + k) * 128 + n]);
        }
        __syncthreads();
#pragma unroll
        for (int ks = 0; ks < 2; ks++) {
            int kb = chunk * 16 + ks * 8;
            unsigned a0 = As[wm * 16 + g][kb + t4];
            unsigned a1 = As[wm * 16 + g + 8][kb + t4];
            unsigned a2 = As[wm * 16 + g][kb + t4 + 4];
            unsigned a3 = As[wm * 16 + g + 8][kb + t4 + 4];
#pragma unroll
            for (int tile = 0; tile < 8; tile++) {
                int n0 = wn * 64 + tile * 8;
                unsigned b0 = Ws[ks * 8 + t4][n0 + g];
                unsigned bb = Ws[ks * 8 + t4 + 4][n0 + g];
                mma_tf32(acc[tile], a0, a1, a2, a3, b0, bb);
            }
        }
        __syncthreads();
    }

    // ---- epilogue: bias + ReLU + W2 projection, all in registers ----
    float tA0 = 0.f, tA1 = 0.f, tB0 = 0.f, tB1 = 0.f;
#pragma unroll
    for (int tile = 0; tile < 8; tile++) {
        int c0 = wn * 64 + tile * 8 + t4 * 2;
        float bias0 = b1s[c0], bias1 = b1s[c0 + 1];
        float h00 = fmaxf(acc[tile][0] + bias0, 0.f);
        float h01 = fmaxf(acc[tile][1] + bias1, 0.f);
        float h10 = fmaxf(acc[tile][2] + bias0, 0.f);
        float h11 = fmaxf(acc[tile][3] + bias1, 0.f);
        float w00 = W2s[c0 * 2 + 0], w01 = W2s[c0 * 2 + 1];
        float w10 = W2s[(c0 + 1) * 2 + 0], w11 = W2s[(c0 + 1) * 2 + 1];
        tA0 += h00 * w00 + h01 * w10;
        tA1 += h00 * w01 + h01 * w11;
        tB0 += h10 * w00 + h11 * w10;
        tB1 += h10 * w01 + h11 * w11;
    }
    tA0 += __shfl_xor_sync(0xffffffffu, tA0, 1); tA0 += __shfl_xor_sync(0xffffffffu, tA0, 2);
    tA1 += __shfl_xor_sync(0xffffffffu, tA1, 1); tA1 += __shfl_xor_sync(0xffffffffu, tA1, 2);
    tB0 += __shfl_xor_sync(0xffffffffu, tB0, 1); tB0 += __shfl_xor_sync(0xffffffffu, tB0, 2);
    tB1 += __shfl_xor_sync(0xffffffffu, tB1, 1); tB1 += __shfl_xor_sync(0xffffffffu, tB1, 2);
    if (t4 == 0) {
        int rA = row0 + wm * 16 + g;
        int rB = rA + 8;
        if (rA < N_NODES) {
            atomicAdd(&g_t[rA * 2 + 0], tA0);
            atomicAdd(&g_t[rA * 2 + 1], tA1);
        }
        if (rB < N_NODES) {
            atomicAdd(&g_t[rB * 2 + 0], tB0);
            atomicAdd(&g_t[rB * 2 + 1], tB1);
        }
    }
}

// layer-2 aggregation (CSR, no atomics) fused with mean-pool accumulation
__global__ void k_agg2_pool(const float* __restrict__ b2) {
    __shared__ float sp[NG * NC];
    __shared__ float sc[NG];
    int tid = threadIdx.x;
    if (tid < NG * NC) sp[tid] = 0.f;
    if (tid < NG)      sc[tid] = 0.f;
    __syncthreads();
    int i = blockIdx.x * blockDim.x + tid;
    if (i < N_NODES) {
        int start = g_ptr[i];
        int deg = g_cnt_hist[i];
        float a0 = 0.f, a1 = 0.f;
        int j = 0;
        for (; j + 2 <= deg; j += 2) {
            int r0 = g_erow[start + j];
            int r1 = g_erow[start + j + 1];
            float w0 = g_dinv[r0], w1 = g_dinv[r1];
            float2 v0 = *(const float2*)&g_t[r0 * 2];
            float2 v1 = *(const float2*)&g_t[r1 * 2];
            a0 += w0 * v0.x + w1 * v1.x;
            a1 += w0 * v0.y + w1 * v1.y;
        }
        if (j < deg) {
            int r0 = g_erow[start + j];
            float w0 = g_dinv[r0];
            float2 v0 = *(const float2*)&g_t[r0 * 2];
            a0 += w0 * v0.x; a1 += w0 * v0.y;
        }
        float dc = g_dinv[i];
        a0 = a0 * dc + b2[0];
        a1 = a1 * dc + b2[1];
        int b = g_batch[i];
        atomicAdd(&sp[b * 2 + 0], a0);
        atomicAdd(&sp[b * 2 + 1], a1);
        atomicAdd(&sc[b], 1.f);
    }
    __syncthreads();
    if (tid < NG * NC && sp[tid] != 0.f) atomicAdd(&g_pool[tid], sp[tid]);
    if (tid < NG && sc[tid] != 0.f)      atomicAdd(&g_gcnt[tid], sc[tid]);
}

__global__ void k_final(float* __restrict__ out) {
    int g = threadIdx.x;
    if (g >= NG) return;
    float cnt = g_gcnt[g];
    float m = fmaxf(cnt, 1.0f);
    float p0 = g_pool[g * 2 + 0] / m;
    float p1 = g_pool[g * 2 + 1] / m;
    float mx = fmaxf(p0, p1);
    float lse = mx + logf(expf(p0 - mx) + expf(p1 - mx));
    out[g * 2 + 0] = p0 - lse;
    out[g * 2 + 1] = p1 - lse;
}

// ---------------- launch ----------------
extern "C" void kernel_launch(void* const* d_in, const int* in_sizes, int n_in,
                              void* d_out, int out_size) {
    const float* x     = (const float*)d_in[0];
    const void*  ei    = d_in[1];
    const void*  batch = d_in[2];
    const float* W1    = (const float*)d_in[3];
    const float* b1    = (const float*)d_in[4];
    const float* W2    = (const float*)d_in[5];
    const float* b2    = (const float*)d_in[6];
    float* out = (float*)d_out;

    k_detect<<<1, 32>>>((const unsigned int*)ei);
    k_zero_cvt<<<(N_NODES + 255) / 256, 256>>>(batch);
    k_build<<<(E_TOT + 255) / 256, 256>>>(ei);
    k_scan1<<<N_SCAN_BLK, SCAN_BS>>>();
    k_scan2<<<1, 512>>>();
    k_scan3<<<(N_NODES + 255) / 256, 256>>>();
    k_fill<<<(E_TOT + 255) / 256, 256>>>();
    k_fused<<<(N_NODES + 63) / 64, 256>>>(x, W1, b1, W2);
    k_agg2_pool<<<(N_NODES + 255) / 256, 256>>>(b2);
    k_final<<<1, 32>>>(out);
}

// round 8
// speedup vs baseline: 3.4514x; 1.0428x over previous
#include <cuda_runtime.h>
#include <cuda_bf16.h>
#include <math.h>

#define N_NODES 100000
#define N_EDGES 800000
#define E_TOT   900000   // edges + self loops
#define NH 128
#define NC 2
#define NG 16
#define SCAN_BS 256
#define N_SCAN_BLK ((N_NODES + SCAN_BS - 1) / SCAN_BS)   // 391

// ---------------- scratch (device globals; no allocation) ----------------
__device__ int   g_is64;
__device__ int   g_row[E_TOT];
__device__ int   g_col[E_TOT];
__device__ int   g_cnt_hist[N_NODES];   // degree (incl. self loop)
__device__ int   g_ptr[N_NODES];        // CSR start
__device__ int   g_cursor[N_NODES];
__device__ unsigned long long g_desc[N_SCAN_BLK];  // lookback descriptors
__device__ float g_dinv[N_NODES];
__device__ int   g_erow[E_TOT];         // source row per CSR slot
__device__ int   g_batch[N_NODES];
__device__ __nv_bfloat16 g_xbf[(size_t)N_NODES * NH];  // x in bf16
__device__ float g_t[N_NODES * NC];     // h@W2 (atomic partial sums)
__device__ float g_pool[NG * NC];
__device__ float g_gcnt[NG];

// ---------------- helpers ----------------
__device__ __forceinline__ void mma_bf16(float* d, unsigned a0, unsigned a1,
                                         unsigned a2, unsigned a3,
                                         unsigned b0, unsigned b1) {
    asm volatile(
        "mma.sync.aligned.m16n8k16.row.col.f32.bf16.bf16.f32 "
        "{%0,%1,%2,%3}, {%4,%5,%6,%7}, {%8,%9}, {%0,%1,%2,%3};"
        : "+f"(d[0]), "+f"(d[1]), "+f"(d[2]), "+f"(d[3])
        : "r"(a0), "r"(a1), "r"(a2), "r"(a3), "r"(b0), "r"(b1));
}

__device__ __forceinline__ int warp_incl_scan(int v, int lane) {
#pragma unroll
    for (int off = 1; off < 32; off <<= 1) {
        int t = __shfl_up_sync(0xffffffffu, v, off);
        if (lane >= off) v += t;
    }
    return v;
}

__device__ __forceinline__ unsigned pack_bf16x2(float a, float b) {
    __nv_bfloat162 p = __float22bfloat162_rn(make_float2(a, b));
    return *(unsigned*)&p;
}

// ---------------- kernels ----------------

// Detect int64 vs int32 index dtype (warp-parallel).
__global__ void k_detect(const unsigned int* __restrict__ e) {
    int lane = threadIdx.x;
    unsigned v = 0;
#pragma unroll
    for (int i = 0; i < 8; i++) v |= e[2 * (lane + 32 * i) + 1];
    int any = __any_sync(0xffffffffu, v != 0u);
    if (lane == 0) g_is64 = !any;
}

// fused: x -> bf16 conversion, zero scratch, batch convert, desc zero
__global__ void k_prep(const float* __restrict__ x, const void* __restrict__ bp) {
    int i = blockIdx.x * blockDim.x + threadIdx.x;
    size_t base = (size_t)i * 4;
    if (base < (size_t)N_NODES * NH) {
        float4 v = *(const float4*)&x[base];
        unsigned u0 = pack_bf16x2(v.x, v.y);
        unsigned u1 = pack_bf16x2(v.z, v.w);
        *(uint2*)&g_xbf[base] = make_uint2(u0, u1);
    }
    if (i < N_NODES) {
        g_cnt_hist[i] = 0;
        g_t[2 * i + 0] = 0.f;
        g_t[2 * i + 1] = 0.f;
        g_batch[i] = g_is64 ? (int)((const long long*)bp)[i] : ((const int*)bp)[i];
    }
    if (i < N_SCAN_BLK) g_desc[i] = 0ull;
    if (i < NG * NC)    g_pool[i] = 0.f;
    if (i < NG)         g_gcnt[i] = 0.f;
}

__global__ void k_build(const void* __restrict__ ep) {
    int e = blockIdx.x * blockDim.x + threadIdx.x;
    if (e >= E_TOT) return;
    int r, c;
    if (e < N_EDGES) {
        if (g_is64) { const long long* p = (const long long*)ep; r = (int)p[e]; c = (int)p[N_EDGES + e]; }
        else        { const int*       p = (const int*)ep;       r = p[e];      c = p[N_EDGES + e]; }
    } else {
        r = c = e - N_EDGES;  // self loop
    }
    g_row[e] = r; g_col[e] = c;
    atomicAdd(&g_cnt_hist[c], 1);
}

// single-pass decoupled-lookback exclusive scan of g_cnt_hist
// fused with g_ptr/g_cursor/g_dinv initialization.
// flags (bits 32+): 1 = aggregate published, 2 = inclusive prefix published
__global__ void k_scan_lb() {
    __shared__ int wsum[8];
    __shared__ int s_exc;
    int tid = threadIdx.x, lane = tid & 31, wid = tid >> 5;
    int bid = blockIdx.x;
    int i = bid * SCAN_BS + tid;

    int v = (i < N_NODES) ? g_cnt_hist[i] : 0;
    int s = warp_incl_scan(v, lane);
    if (lane == 31) wsum[wid] = s;
    __syncthreads();
    if (wid == 0) {
        int w = (lane < 8) ? wsum[lane] : 0;
        w = warp_incl_scan(w, lane);
        if (lane < 8) wsum[lane] = w;
    }
    __syncthreads();
    int base_in = (wid > 0) ? wsum[wid - 1] : 0;
    int total = wsum[7];

    if (tid == 0) {
        s_exc = 0;
        unsigned long long pk = (bid == 0)
            ? ((2ull << 32) | (unsigned)total)
            : ((1ull << 32) | (unsigned)total);
        __threadfence();
        *(volatile unsigned long long*)&g_desc[bid] = pk;
    }
    __syncthreads();

    if (bid > 0 && wid == 0) {
        int sum = 0;
        int base_j = bid - 1;
        while (true) {
            int j = base_j - lane;
            unsigned long long d = 0;
            if (j >= 0) {
                do { d = *(volatile unsigned long long*)&g_desc[j]; }
                while ((unsigned)(d >> 32) == 0u);
            }
            unsigned f  = (j >= 0) ? (unsigned)(d >> 32) : 2u;
            int val     = (j >= 0) ? (int)(unsigned)d : 0;
            unsigned incmask = __ballot_sync(0xffffffffu, f == 2u);
            if (incmask) {
                int firstinc = __ffs(incmask) - 1;   // closest inclusive
                int contrib = (lane <= firstinc) ? val : 0;
#pragma unroll
                for (int off = 16; off > 0; off >>= 1)
                    contrib += __shfl_xor_sync(0xffffffffu, contrib, off);
                sum += contrib;
                break;
            } else {
                int contrib = val;
#pragma unroll
                for (int off = 16; off > 0; off >>= 1)
                    contrib += __shfl_xor_sync(0xffffffffu, contrib, off);
                sum += contrib;
                base_j -= 32;
            }
        }
        if (lane == 0) {
            s_exc = sum;
            __threadfence();
            *(volatile unsigned long long*)&g_desc[bid] =
                (2ull << 32) | (unsigned)(sum + total);
        }
    }
    __syncthreads();

    if (i < N_NODES) {
        int p = s_exc + base_in + s - v;   // exclusive prefix
        g_ptr[i] = p;
        g_cursor[i] = p;
        float d = (float)v;
        g_dinv[i] = (d > 0.f) ? rsqrtf(d) : 0.f;
    }
}

__global__ void k_fill() {
    int e = blockIdx.x * blockDim.x + threadIdx.x;
    if (e >= E_TOT) return;
    int c = g_col[e];
    int slot = atomicAdd(&g_cursor[c], 1);
    g_erow[slot] = g_row[e];
}

// ---------------------------------------------------------------------------
// Fused: aggregate (Â x) from bf16 features into smem (bf16), BF16 tensor-core
// GEMM with W1, epilogue bias+ReLU, W2 projection in registers -> g_t atomics.
// ---------------------------------------------------------------------------
__global__ __launch_bounds__(256, 3) void k_fused(const float* __restrict__ W1,
                                                  const float* __restrict__ b1,
                                                  const float* __restrict__ W2) {
    __shared__ unsigned As2[64][68];   // bf16x2 aggregated features (k2 = k/2)
    __shared__ unsigned Ws2[8][136];   // bf16x2 W1 chunk (k2 within chunk)
    __shared__ float W2s[NH * NC];
    __shared__ float b1s[NH];

    int tid = threadIdx.x, wid = tid >> 5, lane = tid & 31;
    int row0 = blockIdx.x * 64;

    if (tid < NH) b1s[tid] = b1[tid];
    W2s[tid] = W2[tid];

    // ---- stage A: aggregation, warp per node, 4-deep edge unroll (bf16 rows) ----
    for (int i = 0; i < 8; i++) {
        int rl = wid * 8 + i;
        int node = row0 + rl;
        float4 acc = make_float4(0.f, 0.f, 0.f, 0.f);
        if (node < N_NODES) {
            int start = g_ptr[node];
            int deg = g_cnt_hist[node];
            float dc = g_dinv[node];
            int j = 0;
            for (; j + 4 <= deg; j += 4) {
                int r0 = g_erow[start + j];
                int r1 = g_erow[start + j + 1];
                int r2 = g_erow[start + j + 2];
                int r3 = g_erow[start + j + 3];
                float w0 = g_dinv[r0], w1 = g_dinv[r1];
                float w2 = g_dinv[r2], w3 = g_dinv[r3];
                uint2 u0 = *((const uint2*)&g_xbf[(size_t)r0 * NH] + lane);
                uint2 u1 = *((const uint2*)&g_xbf[(size_t)r1 * NH] + lane);
                uint2 u2 = *((const uint2*)&g_xbf[(size_t)r2 * NH] + lane);
                uint2 u3 = *((const uint2*)&g_xbf[(size_t)r3 * NH] + lane);
                float2 a0 = __bfloat1622float2(*(__nv_bfloat162*)&u0.x);
                float2 b0 = __bfloat1622float2(*(__nv_bfloat162*)&u0.y);
                float2 a1 = __bfloat1622float2(*(__nv_bfloat162*)&u1.x);
                float2 b1_ = __bfloat1622float2(*(__nv_bfloat162*)&u1.y);
                float2 a2 = __bfloat1622float2(*(__nv_bfloat162*)&u2.x);
                float2 b2 = __bfloat1622float2(*(__nv_bfloat162*)&u2.y);
                float2 a3 = __bfloat1622float2(*(__nv_bfloat162*)&u3.x);
                float2 b3 = __bfloat1622float2(*(__nv_bfloat162*)&u3.y);
                acc.x += w0 * a0.x + w1 * a1.x + w2 * a2.x + w3 * a3.x;
                acc.y += w0 * a0.y + w1 * a1.y + w2 * a2.y + w3 * a3.y;
                acc.z += w0 * b0.x + w1 * b1_.x + w2 * b2.x + w3 * b3.x;
                acc.w += w0 * b0.y + w1 * b1_.y + w2 * b2.y + w3 * b3.y;
            }
            for (; j < deg; j++) {
                int r0 = g_erow[start + j];
                float w0 = g_dinv[r0];
                uint2 u0 = *((const uint2*)&g_xbf[(size_t)r0 * NH] + lane);
                float2 a0 = __bfloat1622float2(*(__nv_bfloat162*)&u0.x);
                float2 b0 = __bfloat1622float2(*(__nv_bfloat162*)&u0.y);
                acc.x += w0 * a0.x; acc.y += w0 * a0.y;
                acc.z += w0 * b0.x; acc.w += w0 * b0.y;
            }
            acc.x *= dc; acc.y *= dc; acc.z *= dc; acc.w *= dc;
        }
        // lane covers cols lane*4 .. lane*4+3  ->  k2 words lane*2, lane*2+1
        unsigned p0 = pack_bf16x2(acc.x, acc.y);
        unsigned p1 = pack_bf16x2(acc.z, acc.w);
        *(uint2*)&As2[rl][lane * 2] = make_uint2(p0, p1);
    }
    __syncthreads();

    // ---- stage B: BF16 MMA m16n8k16. warp grid 4(m) x 2(n); warp tile 16x64 ----
    int wm = wid >> 1, wn = wid & 1;
    int g = lane >> 2, t4 = lane & 3;
    float acc[8][4];
#pragma unroll
    for (int t = 0; t < 8; t++)
#pragma unroll
        for (int j = 0; j < 4; j++) acc[t][j] = 0.f;

    for (int chunk = 0; chunk < 8; chunk++) {   // K in chunks of 16
#pragma unroll
        for (int t = 0; t < 4; t++) {
            int li = tid + t * 256;
            int k2 = li >> 7, n = li & 127;
            float f0 = W1[(chunk * 16 + 2 * k2) * 128 + n];
            float f1 = W1[(chunk * 16 + 2 * k2 + 1) * 128 + n];
            Ws2[k2][n] = pack_bf16x2(f0, f1);
        }
        __syncthreads();
        unsigned a0 = As2[wm * 16 + g][chunk * 8 + t4];
        unsigned a1 = As2[wm * 16 + g + 8][chunk * 8 + t4];
        unsigned a2 = As2[wm * 16 + g][chunk * 8 + t4 + 4];
        unsigned a3 = As2[wm * 16 + g + 8][chunk * 8 + t4 + 4];
#pragma unroll
        for (int tile = 0; tile < 8; tile++) {
            int n0 = wn * 64 + tile * 8;
            unsigned b0 = Ws2[t4][n0 + g];
            unsigned bb = Ws2[t4 + 4][n0 + g];
            mma_bf16(acc[tile], a0, a1, a2, a3, b0, bb);
        }
        __syncthreads();
    }

    // ---- epilogue: bias + ReLU + W2 projection, all in registers ----
    float tA0 = 0.f, tA1 = 0.f, tB0 = 0.f, tB1 = 0.f;
#pragma unroll
    for (int tile = 0; tile < 8; tile++) {
        int c0 = wn * 64 + tile * 8 + t4 * 2;
        float bias0 = b1s[c0], bias1 = b1s[c0 + 1];
        float h00 = fmaxf(acc[tile][0] + bias0, 0.f);
        float h01 = fmaxf(acc[tile][1] + bias1, 0.f);
        float h10 = fmaxf(acc[tile][2] + bias0, 0.f);
        float h11 = fmaxf(acc[tile][3] + bias1, 0.f);
        float w00 = W2s[c0 * 2 + 0], w01 = W2s[c0 * 2 + 1];
        float w10 = W2s[(c0 + 1) * 2 + 0], w11 = W2s[(c0 + 1) * 2 + 1];
        tA0 += h00 * w00 + h01 * w10;
        tA1 += h00 * w01 + h01 * w11;
        tB0 += h10 * w00 + h11 * w10;
        tB1 += h10 * w01 + h11 * w11;
    }
    tA0 += __shfl_xor_sync(0xffffffffu, tA0, 1); tA0 += __shfl_xor_sync(0xffffffffu, tA0, 2);
    tA1 += __shfl_xor_sync(0xffffffffu, tA1, 1); tA1 += __shfl_xor_sync(0xffffffffu, tA1, 2);
    tB0 += __shfl_xor_sync(0xffffffffu, tB0, 1); tB0 += __shfl_xor_sync(0xffffffffu, tB0, 2);
    tB1 += __shfl_xor_sync(0xffffffffu, tB1, 1); tB1 += __shfl_xor_sync(0xffffffffu, tB1, 2);
    if (t4 == 0) {
        int rA = row0 + wm * 16 + g;
        int rB = rA + 8;
        if (rA < N_NODES) {
            atomicAdd(&g_t[rA * 2 + 0], tA0);
            atomicAdd(&g_t[rA * 2 + 1], tA1);
        }
        if (rB < N_NODES) {
            atomicAdd(&g_t[rB * 2 + 0], tB0);
            atomicAdd(&g_t[rB * 2 + 1], tB1);
        }
    }
}

// layer-2 aggregation (CSR, no atomics) fused with mean-pool accumulation
__global__ void k_agg2_pool(const float* __restrict__ b2) {
    __shared__ float sp[NG * NC];
    __shared__ float sc[NG];
    int tid = threadIdx.x;
    if (tid < NG * NC) sp[tid] = 0.f;
    if (tid < NG)      sc[tid] = 0.f;
    __syncthreads();
    int i = blockIdx.x * blockDim.x + tid;
    if (i < N_NODES) {
        int start = g_ptr[i];
        int deg = g_cnt_hist[i];
        float a0 = 0.f, a1 = 0.f;
        int j = 0;
        for (; j + 2 <= deg; j += 2) {
            int r0 = g_erow[start + j];
            int r1 = g_erow[start + j + 1];
            float w0 = g_dinv[r0], w1 = g_dinv[r1];
            float2 v0 = *(const float2*)&g_t[r0 * 2];
            float2 v1 = *(const float2*)&g_t[r1 * 2];
            a0 += w0 * v0.x + w1 * v1.x;
            a1 += w0 * v0.y + w1 * v1.y;
        }
        if (j < deg) {
            int r0 = g_erow[start + j];
            float w0 = g_dinv[r0];
            float2 v0 = *(const float2*)&g_t[r0 * 2];
            a0 += w0 * v0.x; a1 += w0 * v0.y;
        }
        float dc = g_dinv[i];
        a0 = a0 * dc + b2[0];
        a1 = a1 * dc + b2[1];
        int b = g_batch[i];
        atomicAdd(&sp[b * 2 + 0], a0);
        atomicAdd(&sp[b * 2 + 1], a1);
        atomicAdd(&sc[b], 1.f);
    }
    __syncthreads();
    if (tid < NG * NC && sp[tid] != 0.f) atomicAdd(&g_pool[tid], sp[tid]);
    if (tid < NG && sc[tid] != 0.f)      atomicAdd(&g_gcnt[tid], sc[tid]);
}

__global__ void k_final(float* __restrict__ out) {
    int g = threadIdx.x;
    if (g >= NG) return;
    float cnt = g_gcnt[g];
    float m = fmaxf(cnt, 1.0f);
    float p0 = g_pool[g * 2 + 0] / m;
    float p1 = g_pool[g * 2 + 1] / m;
    float mx = fmaxf(p0, p1);
    float lse = mx + logf(expf(p0 - mx) + expf(p1 - mx));
    out[g * 2 + 0] = p0 - lse;
    out[g * 2 + 1] = p1 - lse;
}

// ---------------- launch ----------------
extern "C" void kernel_launch(void* const* d_in, const int* in_sizes, int n_in,
                              void* d_out, int out_size) {
    const float* x     = (const float*)d_in[0];
    const void*  ei    = d_in[1];
    const void*  batch = d_in[2];
    const float* W1    = (const float*)d_in[3];
    const float* b1    = (const float*)d_in[4];
    const float* W2    = (const float*)d_in[5];
    const float* b2    = (const float*)d_in[6];
    float* out = (float*)d_out;

    k_detect<<<1, 32>>>((const unsigned int*)ei);
    k_prep<<<((N_NODES * NH / 4) + 255) / 256, 256>>>(x, batch);
    k_build<<<(E_TOT + 255) / 256, 256>>>(ei);
    k_scan_lb<<<N_SCAN_BLK, SCAN_BS>>>();
    k_fill<<<(E_TOT + 255) / 256, 256>>>();
    k_fused<<<(N_NODES + 63) / 64, 256>>>(W1, b1, W2);
    k_agg2_pool<<<(N_NODES + 255) / 256, 256>>>(b2);
    k_final<<<1, 32>>>(out);
}

// round 10
// speedup vs baseline: 3.9644x; 1.1486x over previous
#include <cuda_runtime.h>
#include <cuda_bf16.h>
#include <math.h>

#define N_NODES 100000
#define N_EDGES 800000
#define E_TOT   900000   // edges + self loops
#define NH 128
#define NC 2
#define NG 16
#define SCAN_BS 256
#define N_SCAN_BLK ((N_NODES + SCAN_BS - 1) / SCAN_BS)   // 391

// ---------------- scratch (device globals; no allocation) ----------------
__device__ int   g_is64;
__device__ int   g_row[E_TOT];
__device__ int   g_col[E_TOT];
__device__ int   g_cnt_hist[N_NODES];   // degree (incl. self loop)
__device__ int   g_ptr[N_NODES];        // CSR start
__device__ int   g_cursor[N_NODES];
__device__ int   g_blksum[512];
__device__ int   g_blkoff[512];
__device__ float g_dinv[N_NODES];
__device__ uint2 g_epack[E_TOT];        // {src row, dinv[src] bits} per CSR slot
__device__ int   g_batch[N_NODES];
__device__ __nv_bfloat16 g_xbf[(size_t)N_NODES * NH];  // x in bf16
__device__ unsigned g_w1bf[64 * 128];   // W1 packed bf16x2 along k (k2 x n)
__device__ unsigned g_aggbf[(size_t)N_NODES * 64];     // Ax in bf16x2 (64 words/row)
__device__ float g_t[N_NODES * NC];     // h@W2
__device__ float g_pool[NG * NC];
__device__ float g_gcnt[NG];

// ---------------- helpers ----------------
__device__ __forceinline__ void mma_bf16(float* d, unsigned a0, unsigned a1,
                                         unsigned a2, unsigned a3,
                                         unsigned b0, unsigned b1) {
    asm volatile(
        "mma.sync.aligned.m16n8k16.row.col.f32.bf16.bf16.f32 "
        "{%0,%1,%2,%3}, {%4,%5,%6,%7}, {%8,%9}, {%0,%1,%2,%3};"
        : "+f"(d[0]), "+f"(d[1]), "+f"(d[2]), "+f"(d[3])
        : "r"(a0), "r"(a1), "r"(a2), "r"(a3), "r"(b0), "r"(b1));
}

__device__ __forceinline__ int warp_incl_scan(int v, int lane) {
#pragma unroll
    for (int off = 1; off < 32; off <<= 1) {
        int t = __shfl_up_sync(0xffffffffu, v, off);
        if (lane >= off) v += t;
    }
    return v;
}

__device__ __forceinline__ unsigned pack_bf16x2(float a, float b) {
    __nv_bfloat162 p = __float22bfloat162_rn(make_float2(a, b));
    return *(unsigned*)&p;
}

// ---------------- kernels ----------------

__global__ void k_detect(const unsigned int* __restrict__ e) {
    int lane = threadIdx.x;
    unsigned v = 0;
#pragma unroll
    for (int i = 0; i < 8; i++) v |= e[2 * (lane + 32 * i) + 1];
    int any = __any_sync(0xffffffffu, v != 0u);
    if (lane == 0) g_is64 = !any;
}

// fused: x->bf16, W1->bf16x2 pack, zero scratch, batch convert
__global__ void k_prep(const float* __restrict__ x, const void* __restrict__ bp,
                       const float* __restrict__ W1) {
    int i = blockIdx.x * blockDim.x + threadIdx.x;
    size_t base = (size_t)i * 4;
    if (base < (size_t)N_NODES * NH) {
        float4 v = *(const float4*)&x[base];
        unsigned u0 = pack_bf16x2(v.x, v.y);
        unsigned u1 = pack_bf16x2(v.z, v.w);
        *(uint2*)&g_xbf[base] = make_uint2(u0, u1);
    }
    if (i < 64 * 128) {
        int k2 = i >> 7, n = i & 127;
        g_w1bf[i] = pack_bf16x2(W1[(2 * k2) * 128 + n], W1[(2 * k2 + 1) * 128 + n]);
    }
    if (i < N_NODES) {
        g_cnt_hist[i] = 0;
        g_batch[i] = g_is64 ? (int)((const long long*)bp)[i] : ((const int*)bp)[i];
    }
    if (i < NG * NC) g_pool[i] = 0.f;
    if (i < NG)      g_gcnt[i] = 0.f;
}

__global__ void k_build(const void* __restrict__ ep) {
    int e = blockIdx.x * blockDim.x + threadIdx.x;
    if (e >= E_TOT) return;
    int r, c;
    if (e < N_EDGES) {
        if (g_is64) { const long long* p = (const long long*)ep; r = (int)p[e]; c = (int)p[N_EDGES + e]; }
        else        { const int*       p = (const int*)ep;       r = p[e];      c = p[N_EDGES + e]; }
    } else {
        r = c = e - N_EDGES;  // self loop
    }
    g_row[e] = r; g_col[e] = c;
    atomicAdd(&g_cnt_hist[c], 1);
}

// two-level exclusive scan of g_cnt_hist -> g_ptr (shuffle-based)
__global__ void k_scan1() {
    __shared__ int wsum[8];
    int tid = threadIdx.x, lane = tid & 31, wid = tid >> 5;
    int i = blockIdx.x * SCAN_BS + tid;
    int v = (i < N_NODES) ? g_cnt_hist[i] : 0;
    int s = warp_incl_scan(v, lane);
    if (lane == 31) wsum[wid] = s;
    __syncthreads();
    if (wid == 0) {
        int w = (lane < 8) ? wsum[lane] : 0;
        w = warp_incl_scan(w, lane);
        if (lane < 8) wsum[lane] = w;
    }
    __syncthreads();
    int base = (wid > 0) ? wsum[wid - 1] : 0;
    if (i < N_NODES) g_ptr[i] = base + s - v;
    if (tid == SCAN_BS - 1) g_blksum[blockIdx.x] = base + s;
}

__global__ void k_scan2() {
    __shared__ int wsum[16];
    int tid = threadIdx.x, lane = tid & 31, wid = tid >> 5;
    int v = (tid < N_SCAN_BLK) ? g_blksum[tid] : 0;
    int s = warp_incl_scan(v, lane);
    if (lane == 31) wsum[wid] = s;
    __syncthreads();
    if (wid == 0) {
        int w = (lane < 16) ? wsum[lane] : 0;
        w = warp_incl_scan(w, lane);
        if (lane < 16) wsum[lane] = w;
    }
    __syncthreads();
    int base = (wid > 0) ? wsum[wid - 1] : 0;
    g_blkoff[tid] = base + s - v;
}

__global__ void k_scan3() {
    int i = blockIdx.x * blockDim.x + threadIdx.x;
    if (i >= N_NODES) return;
    int p = g_ptr[i] + g_blkoff[i >> 8];
    g_ptr[i] = p;
    g_cursor[i] = p;
    float d = (float)g_cnt_hist[i];
    g_dinv[i] = (d > 0.f) ? rsqrtf(d) : 0.f;
}

// fill CSR with packed {src, dinv[src]} records
__global__ void k_fill() {
    int e = blockIdx.x * blockDim.x + threadIdx.x;
    if (e >= E_TOT) return;
    int c = g_col[e];
    int r = g_row[e];
    float w = g_dinv[r];
    int slot = atomicAdd(&g_cursor[c], 1);
    g_epack[slot] = make_uint2((unsigned)r, __float_as_uint(w));
}

// ---------------------------------------------------------------------------
// agg = Â x (bf16): warp per node, high occupancy, no smem.
// ---------------------------------------------------------------------------
__global__ void k_agg1() {
    int gt = blockIdx.x * blockDim.x + threadIdx.x;
    int w = gt >> 5, lane = gt & 31;
    if (w >= N_NODES) return;
    int start = g_ptr[w];
    int deg = g_cnt_hist[w];
    float dc = g_dinv[w];
    float4 acc = make_float4(0.f, 0.f, 0.f, 0.f);
    int j = 0;
    for (; j + 4 <= deg; j += 4) {
        uint2 e0 = g_epack[start + j];
        uint2 e1 = g_epack[start + j + 1];
        uint2 e2 = g_epack[start + j + 2];
        uint2 e3 = g_epack[start + j + 3];
        float w0 = __uint_as_float(e0.y), w1 = __uint_as_float(e1.y);
        float w2 = __uint_as_float(e2.y), w3 = __uint_as_float(e3.y);
        uint2 u0 = *((const uint2*)&g_xbf[(size_t)e0.x * NH] + lane);
        uint2 u1 = *((const uint2*)&g_xbf[(size_t)e1.x * NH] + lane);
        uint2 u2 = *((const uint2*)&g_xbf[(size_t)e2.x * NH] + lane);
        uint2 u3 = *((const uint2*)&g_xbf[(size_t)e3.x * NH] + lane);
        float2 a0 = __bfloat1622float2(*(__nv_bfloat162*)&u0.x);
        float2 b0 = __bfloat1622float2(*(__nv_bfloat162*)&u0.y);
        float2 a1 = __bfloat1622float2(*(__nv_bfloat162*)&u1.x);
        float2 b1 = __bfloat1622float2(*(__nv_bfloat162*)&u1.y);
        float2 a2 = __bfloat1622float2(*(__nv_bfloat162*)&u2.x);
        float2 b2 = __bfloat1622float2(*(__nv_bfloat162*)&u2.y);
        float2 a3 = __bfloat1622float2(*(__nv_bfloat162*)&u3.x);
        float2 b3 = __bfloat1622float2(*(__nv_bfloat162*)&u3.y);
        acc.x += w0 * a0.x + w1 * a1.x + w2 * a2.x + w3 * a3.x;
        acc.y += w0 * a0.y + w1 * a1.y + w2 * a2.y + w3 * a3.y;
        acc.z += w0 * b0.x + w1 * b1.x + w2 * b2.x + w3 * b3.x;
        acc.w += w0 * b0.y + w1 * b1.y + w2 * b2.y + w3 * b3.y;
    }
    for (; j < deg; j++) {
        uint2 e0 = g_epack[start + j];
        float w0 = __uint_as_float(e0.y);
        uint2 u0 = *((const uint2*)&g_xbf[(size_t)e0.x * NH] + lane);
        float2 a0 = __bfloat1622float2(*(__nv_bfloat162*)&u0.x);
        float2 b0 = __bfloat1622float2(*(__nv_bfloat162*)&u0.y);
        acc.x += w0 * a0.x; acc.y += w0 * a0.y;
        acc.z += w0 * b0.x; acc.w += w0 * b0.y;
    }
    acc.x *= dc; acc.y *= dc; acc.z *= dc; acc.w *= dc;
    unsigned p0 = pack_bf16x2(acc.x, acc.y);
    unsigned p1 = pack_bf16x2(acc.z, acc.w);
    *(uint2*)&g_aggbf[(size_t)w * 64 + lane * 2] = make_uint2(p0, p1);
}

// ---------------------------------------------------------------------------
// Dense bf16 GEMM: h = relu(agg @ W1 + b1); t = h @ W2 fused in registers.
// Whole W1 (bf16x2) cached in smem. The two n-half warps (wn=0/1) each hold
// PARTIAL W2 projections; combine deterministically through smem (round-9 bug
// was plain stores racing between the halves).
// ---------------------------------------------------------------------------
__global__ __launch_bounds__(256, 3) void k_gemm(const float* __restrict__ b1,
                                                 const float* __restrict__ W2) {
    __shared__ unsigned As2[64][68];    // 64 rows x 64 k2-words (+pad)
    __shared__ unsigned Ws2[64][136];   // full W1: 64 k2 x 128 n (+pad)
    __shared__ float W2s[NH * NC];
    __shared__ float b1s[NH];
    __shared__ float tsh[2][64][2];     // per-n-half partial t

    int tid = threadIdx.x, wid = tid >> 5, lane = tid & 31;
    int row0 = blockIdx.x * 64;

    if (tid < NH) b1s[tid] = b1[tid];
    W2s[tid] = W2[tid];

    // load full W1 (2048 uint4)
#pragma unroll
    for (int t = 0; t < 8; t++) {
        int u4 = tid + t * 256;
        int k2 = u4 >> 5, n4 = u4 & 31;
        *(uint4*)&Ws2[k2][n4 * 4] = ((const uint4*)&g_w1bf[k2 * 128])[n4];
    }
    // load A tile (1024 uint4)
#pragma unroll
    for (int t = 0; t < 4; t++) {
        int u4 = tid + t * 256;
        int r = u4 >> 4, c4 = u4 & 15;
        uint4 v = make_uint4(0u, 0u, 0u, 0u);
        if (row0 + r < N_NODES)
            v = ((const uint4*)&g_aggbf[(size_t)(row0 + r) * 64])[c4];
        *(uint4*)&As2[r][c4 * 4] = v;
    }
    __syncthreads();

    int wm = wid >> 1, wn = wid & 1;
    int g = lane >> 2, t4 = lane & 3;
    float acc[8][4];
#pragma unroll
    for (int t = 0; t < 8; t++)
#pragma unroll
        for (int j = 0; j < 4; j++) acc[t][j] = 0.f;

#pragma unroll
    for (int chunk = 0; chunk < 8; chunk++) {
        unsigned a0 = As2[wm * 16 + g][chunk * 8 + t4];
        unsigned a1 = As2[wm * 16 + g + 8][chunk * 8 + t4];
        unsigned a2 = As2[wm * 16 + g][chunk * 8 + t4 + 4];
        unsigned a3 = As2[wm * 16 + g + 8][chunk * 8 + t4 + 4];
#pragma unroll
        for (int tile = 0; tile < 8; tile++) {
            int n0 = wn * 64 + tile * 8;
            unsigned b0 = Ws2[chunk * 8 + t4][n0 + g];
            unsigned bb = Ws2[chunk * 8 + t4 + 4][n0 + g];
            mma_bf16(acc[tile], a0, a1, a2, a3, b0, bb);
        }
    }

    // epilogue: bias + ReLU + W2 projection (partial over this warp's n-half)
    float tA0 = 0.f, tA1 = 0.f, tB0 = 0.f, tB1 = 0.f;
#pragma unroll
    for (int tile = 0; tile < 8; tile++) {
        int c0 = wn * 64 + tile * 8 + t4 * 2;
        float bias0 = b1s[c0], bias1 = b1s[c0 + 1];
        float h00 = fmaxf(acc[tile][0] + bias0, 0.f);
        float h01 = fmaxf(acc[tile][1] + bias1, 0.f);
        float h10 = fmaxf(acc[tile][2] + bias0, 0.f);
        float h11 = fmaxf(acc[tile][3] + bias1, 0.f);
        float w00 = W2s[c0 * 2 + 0], w01 = W2s[c0 * 2 + 1];
        float w10 = W2s[(c0 + 1) * 2 + 0], w11 = W2s[(c0 + 1) * 2 + 1];
        tA0 += h00 * w00 + h01 * w10;
        tA1 += h00 * w01 + h01 * w11;
        tB0 += h10 * w00 + h11 * w10;
        tB1 += h10 * w01 + h11 * w11;
    }
    tA0 += __shfl_xor_sync(0xffffffffu, tA0, 1); tA0 += __shfl_xor_sync(0xffffffffu, tA0, 2);
    tA1 += __shfl_xor_sync(0xffffffffu, tA1, 1); tA1 += __shfl_xor_sync(0xffffffffu, tA1, 2);
    tB0 += __shfl_xor_sync(0xffffffffu, tB0, 1); tB0 += __shfl_xor_sync(0xffffffffu, tB0, 2);
    tB1 += __shfl_xor_sync(0xffffffffu, tB1, 1); tB1 += __shfl_xor_sync(0xffffffffu, tB1, 2);
    if (t4 == 0) {
        int rlA = wm * 16 + g;
        int rlB = rlA + 8;
        tsh[wn][rlA][0] = tA0; tsh[wn][rlA][1] = tA1;
        tsh[wn][rlB][0] = tB0; tsh[wn][rlB][1] = tB1;
    }
    __syncthreads();
    // combine the two n-halves and store (deterministic, each element owned once)
    if (tid < 128) {
        int rl = tid >> 1, c = tid & 1;
        int gr = row0 + rl;
        if (gr < N_NODES)
            g_t[gr * 2 + c] = tsh[0][rl][c] + tsh[1][rl][c];
    }
}

// layer-2 aggregation (CSR, no atomics) fused with mean-pool accumulation
__global__ void k_agg2_pool(const float* __restrict__ b2) {
    __shared__ float sp[NG * NC];
    __shared__ float sc[NG];
    int tid = threadIdx.x;
    if (tid < NG * NC) sp[tid] = 0.f;
    if (tid < NG)      sc[tid] = 0.f;
    __syncthreads();
    int i = blockIdx.x * blockDim.x + tid;
    if (i < N_NODES) {
        int start = g_ptr[i];
        int deg = g_cnt_hist[i];
        float a0 = 0.f, a1 = 0.f;
        int j = 0;
        for (; j + 2 <= deg; j += 2) {
            uint2 e0 = g_epack[start + j];
            uint2 e1 = g_epack[start + j + 1];
            float w0 = __uint_as_float(e0.y), w1 = __uint_as_float(e1.y);
            float2 v0 = *(const float2*)&g_t[e0.x * 2];
            float2 v1 = *(const float2*)&g_t[e1.x * 2];
            a0 += w0 * v0.x + w1 * v1.x;
            a1 += w0 * v0.y + w1 * v1.y;
        }
        if (j < deg) {
            uint2 e0 = g_epack[start + j];
            float w0 = __uint_as_float(e0.y);
            float2 v0 = *(const float2*)&g_t[e0.x * 2];
            a0 += w0 * v0.x; a1 += w0 * v0.y;
        }
        float dc = g_dinv[i];
        a0 = a0 * dc + b2[0];
        a1 = a1 * dc + b2[1];
        int b = g_batch[i];
        atomicAdd(&sp[b * 2 + 0], a0);
        atomicAdd(&sp[b * 2 + 1], a1);
        atomicAdd(&sc[b], 1.f);
    }
    __syncthreads();
    if (tid < NG * NC && sp[tid] != 0.f) atomicAdd(&g_pool[tid], sp[tid]);
    if (tid < NG && sc[tid] != 0.f)      atomicAdd(&g_gcnt[tid], sc[tid]);
}

__global__ void k_final(float* __restrict__ out) {
    int g = threadIdx.x;
    if (g >= NG) return;
    float cnt = g_gcnt[g];
    float m = fmaxf(cnt, 1.0f);
    float p0 = g_pool[g * 2 + 0] / m;
    float p1 = g_pool[g * 2 + 1] / m;
    float mx = fmaxf(p0, p1);
    float lse = mx + logf(expf(p0 - mx) + expf(p1 - mx));
    out[g * 2 + 0] = p0 - lse;
    out[g * 2 + 1] = p1 - lse;
}

// ---------------- launch ----------------
extern "C" void kernel_launch(void* const* d_in, const int* in_sizes, int n_in,
                              void* d_out, int out_size) {
    const float* x     = (const float*)d_in[0];
    const void*  ei    = d_in[1];
    const void*  batch = d_in[2];
    const float* W1    = (const float*)d_in[3];
    const float* b1    = (const float*)d_in[4];
    const float* W2    = (const float*)d_in[5];
    const float* b2    = (const float*)d_in[6];
    float* out = (float*)d_out;

    k_detect<<<1, 32>>>((const unsigned int*)ei);
    k_prep<<<((N_NODES * NH / 4) + 255) / 256, 256>>>(x, batch, W1);
    k_build<<<(E_TOT + 255) / 256, 256>>>(ei);
    k_scan1<<<N_SCAN_BLK, SCAN_BS>>>();
    k_scan2<<<1, 512>>>();
    k_scan3<<<(N_NODES + 255) / 256, 256>>>();
    k_fill<<<(E_TOT + 255) / 256, 256>>>();
    k_agg1<<<(N_NODES * 32 + 255) / 256, 256>>>();
    k_gemm<<<(N_NODES + 63) / 64, 256>>>(b1, W2);
    k_agg2_pool<<<(N_NODES + 255) / 256, 256>>>(b2);
    k_final<<<1, 32>>>(out);
}